// round 14
// baseline (speedup 1.0000x reference)
#include <cuda_runtime.h>
#include <cstdint>

// SPDUnVectorize: x[B, L] packed upper triangle (row-major, incl. diag) ->
// out[B, n, n] symmetric. B=1024, n=256, L=n(n+1)/2=32896.
//
// 128-thread blocks: one 32x32 tile x 2 batches. Warp w owns rows 8w..8w+7
// -> 16 staged LDGs/thread before a 4-warp __syncthreads().
// 32-bit indexing off single bases to cut register pressure (occupancy).
// Early register-direct upper stores; v8 mirror stores.

#define NMAT   256
#define L_IN   32896u
#define BATCH  1024
#define TILE   32
#define NTROW  8
#define NTILES 36
#define PAD    33
#define OUTSZ  65536u   // NMAT*NMAT

__device__ __forceinline__ unsigned tri_off(unsigned r) {
    return r * NMAT - (r * (r - 1u)) / 2u;
}

__device__ __forceinline__ void stg256(float* p, const float* v) {
    asm volatile(
        "st.global.v8.b32 [%0], {%1, %2, %3, %4, %5, %6, %7, %8};"
        :: "l"(p),
           "r"(__float_as_uint(v[0])), "r"(__float_as_uint(v[1])),
           "r"(__float_as_uint(v[2])), "r"(__float_as_uint(v[3])),
           "r"(__float_as_uint(v[4])), "r"(__float_as_uint(v[5])),
           "r"(__float_as_uint(v[6])), "r"(__float_as_uint(v[7]))
        : "memory");
}

__global__ __launch_bounds__(128, 14)
void spd_unvec_kernel(const float* __restrict__ in, float* __restrict__ out) {
    __shared__ float s0[TILE][PAD];
    __shared__ float s1[TILE][PAD];

    const int b0 = blockIdx.y * 2;
    int t = blockIdx.x;

    int ti = 0;
    int rem = NTROW;
    while (t >= rem) { t -= rem; rem--; ti++; }
    const int tj = ti + t;

    const int w    = threadIdx.x >> 5;   // warp 0..3: rows 8w..8w+7
    const int lane = threadIdx.x & 31;   // column within tile

    // single 32-bit-indexed bases
    const float* __restrict__ inb  = in  + (size_t)b0 * L_IN;    // batch b0
    float*       __restrict__ outb = out + (size_t)b0 * OUTSZ;   // batch b0

    // mirror mapping: 128 threads -> 32 rows x 4 v8-chunks (per batch)
    const unsigned mrow = threadIdx.x >> 2;          // 0..31
    const unsigned moc  = (threadIdx.x & 3) << 3;    // 0,8,16,24

    if (ti == tj) {
        const unsigned R = ti * TILE;
        #pragma unroll
        for (int k = 0; k < 8; k++) {
            const unsigned lr = w * 8 + k;
            if ((unsigned)lane >= lr) {
                const unsigned idx = tri_off(R + lr) + lane - lr;
                s0[lr][lane] = inb[idx];
                s1[lr][lane] = inb[idx + L_IN];
            }
        }
        __syncthreads();
        float m0[8], m1[8];
        #pragma unroll
        for (int k = 0; k < 8; k++) {
            const unsigned c = moc + k;
            const bool up = (c >= mrow);
            m0[k] = up ? s0[mrow][c] : s0[c][mrow];
            m1[k] = up ? s1[mrow][c] : s1[c][mrow];
        }
        const unsigned o = (R + mrow) * NMAT + R + moc;
        stg256(&outb[o], m0);
        stg256(&outb[o + OUTSZ], m1);
    } else {
        // Off-diagonal tile (ti < tj): stage 16 loads, then stores.
        const unsigned cb = tj * TILE + lane;
        float v0[8], v1[8];
        unsigned idx0;
        {
            const unsigned r0 = ti * TILE + w * 8;
            idx0 = tri_off(r0) - r0 + cb;
        }
        // row r -> r+1: offset delta = (NMAT-1-r); accumulate to avoid re-mul
        #pragma unroll
        for (int k = 0; k < 8; k++) {
            const unsigned r   = ti * TILE + w * 8 + k;
            const unsigned idx = tri_off(r) - r + cb;
            v0[k] = inb[idx];
            v1[k] = inb[idx + L_IN];
        }
        (void)idx0;
        // Upper tile: direct register stores (coalesced 128B rows) + stage.
        #pragma unroll
        for (int k = 0; k < 8; k++) {
            const unsigned lr = w * 8 + k;
            const unsigned o  = (ti * TILE + lr) * NMAT + cb;
            outb[o]         = v0[k];
            outb[o + OUTSZ] = v1[k];
            s0[lr][lane] = v0[k];
            s1[lr][lane] = v1[k];
        }
        __syncthreads();
        // Mirror tiles: transposed smem reads, one v8 store per batch.
        float m0[8], m1[8];
        #pragma unroll
        for (int k = 0; k < 8; k++) {
            m0[k] = s0[moc + k][mrow];
            m1[k] = s1[moc + k][mrow];
        }
        const unsigned o = (tj * TILE + mrow) * NMAT + ti * TILE + moc;
        stg256(&outb[o], m0);
        stg256(&outb[o + OUTSZ], m1);
    }
}

extern "C" void kernel_launch(void* const* d_in, const int* in_sizes, int n_in,
                              void* d_out, int out_size) {
    const float* in = (const float*)d_in[0];
    float* out = (float*)d_out;
    dim3 grid(NTILES, BATCH / 2);
    dim3 block(128);
    spd_unvec_kernel<<<grid, block>>>(in, out);
}

// round 15
// speedup vs baseline: 1.0020x; 1.0020x over previous
#include <cuda_runtime.h>
#include <cstdint>

// SPDUnVectorize: x[B, L] packed upper triangle (row-major, incl. diag) ->
// out[B, n, n] symmetric. B=1024, n=256, L=n(n+1)/2=32896.
//
// FINAL (= R10 champion): one block = one 32x32 tile x 2 batches.
//  - 8 register-staged, fully-coalesced LDGs per thread (warp = row)
//  - upper tile stored DIRECTLY from load registers before the barrier
//  - single __syncthreads(); mirror via PAD-33 smem, 256-bit stores
// Measured: 61.9us wall, 57.9us kernel, DRAM 75.2% (~6.0 TB/s), occ 93%.
// DRAM mixed read/write turnaround is the binding ceiling (proven across
// occ 69-93%, MLP 8-16/thread, block 128/256, barrier variants).

#define NMAT   256
#define L_IN   32896
#define BATCH  1024
#define TILE   32
#define NTROW  8
#define NTILES 36
#define PAD    33

__device__ __forceinline__ int tri_off(int r) {
    return r * NMAT - (r * (r - 1)) / 2;
}

__device__ __forceinline__ void stg256(float* p, const float* v) {
    asm volatile(
        "st.global.v8.b32 [%0], {%1, %2, %3, %4, %5, %6, %7, %8};"
        :: "l"(p),
           "r"(__float_as_uint(v[0])), "r"(__float_as_uint(v[1])),
           "r"(__float_as_uint(v[2])), "r"(__float_as_uint(v[3])),
           "r"(__float_as_uint(v[4])), "r"(__float_as_uint(v[5])),
           "r"(__float_as_uint(v[6])), "r"(__float_as_uint(v[7]))
        : "memory");
}

__global__ __launch_bounds__(256, 7)
void spd_unvec_kernel(const float* __restrict__ in, float* __restrict__ out) {
    __shared__ float s0[TILE][PAD];
    __shared__ float s1[TILE][PAD];

    const int b0 = blockIdx.y * 2;
    int t = blockIdx.x;

    int ti = 0;
    int rem = NTROW;
    while (t >= rem) { t -= rem; rem--; ti++; }
    const int tj = ti + t;

    const int lane = threadIdx.x & 31;   // column within tile (loads/upper)
    const int wy   = threadIdx.x >> 5;   // 0..7 (base row)

    const float* __restrict__ in0  = in  + (size_t)b0 * L_IN;
    const float* __restrict__ in1  = in0 + L_IN;
    float*       __restrict__ out0 = out + (size_t)b0 * (NMAT * NMAT);
    float*       __restrict__ out1 = out0 + (NMAT * NMAT);

    if (ti == tj) {
        // ---- Diagonal tile, both batches (8/36 tiles) ----
        #pragma unroll
        for (int k = 0; k < 4; k++) {
            const int lr = wy + k * 8;
            const int r  = ti * TILE + lr;
            if (lane >= lr) {
                const int idx = tri_off(r) + lane - lr;
                s0[lr][lane] = in0[idx];
                s1[lr][lane] = in1[idx];
            }
        }
        __syncthreads();
        const int row = threadIdx.x >> 3;
        const int qc  = (threadIdx.x & 7) << 2;
        const int r   = ti * TILE + row;
        float4 v0, v1;
        #pragma unroll
        for (int k = 0; k < 4; k++) {
            const int c  = qc + k;
            const bool up = (c >= row);
            ((float*)&v0)[k] = up ? s0[row][c] : s0[c][row];
            ((float*)&v1)[k] = up ? s1[row][c] : s1[c][row];
        }
        *reinterpret_cast<float4*>(&out0[r * NMAT + ti * TILE + qc]) = v0;
        *reinterpret_cast<float4*>(&out1[r * NMAT + ti * TILE + qc]) = v1;
    } else {
        // ---- Off-diagonal tile (ti < tj), both batches ----
        // Stage all 8 loads (4 rows x 2 batches) in registers first.
        float v0[4], v1[4];
        #pragma unroll
        for (int k = 0; k < 4; k++) {
            const int lr  = wy + k * 8;
            const int r   = ti * TILE + lr;
            const int idx = tri_off(r) - r + tj * TILE + lane;
            v0[k] = in0[idx];
            v1[k] = in1[idx];
        }
        // Upper tile: store DIRECTLY from registers before the barrier.
        #pragma unroll
        for (int k = 0; k < 4; k++) {
            const int lr = wy + k * 8;
            const int r  = ti * TILE + lr;
            out0[r * NMAT + tj * TILE + lane] = v0[k];
            out1[r * NMAT + tj * TILE + lane] = v1[k];
            s0[lr][lane] = v0[k];
            s1[lr][lane] = v1[k];
        }
        __syncthreads();

        // Mirror tile: one 256-bit store per thread.
        const int mb   = threadIdx.x >> 7;           // 0..1 batch
        const int mrow = (threadIdx.x >> 2) & 31;    // 0..31 mirror row
        const int moc  = (threadIdx.x & 3) << 3;     // 0,8,16,24

        float m[8];
        if (mb == 0) {
            #pragma unroll
            for (int k = 0; k < 8; k++) m[k] = s0[moc + k][mrow];
            stg256(&out0[(tj * TILE + mrow) * NMAT + ti * TILE + moc], m);
        } else {
            #pragma unroll
            for (int k = 0; k < 8; k++) m[k] = s1[moc + k][mrow];
            stg256(&out1[(tj * TILE + mrow) * NMAT + ti * TILE + moc], m);
        }
    }
}

extern "C" void kernel_launch(void* const* d_in, const int* in_sizes, int n_in,
                              void* d_out, int out_size) {
    const float* in = (const float*)d_in[0];
    float* out = (float*)d_out;
    dim3 grid(NTILES, BATCH / 2);
    dim3 block(256);
    spd_unvec_kernel<<<grid, block>>>(in, out);
}